// round 9
// baseline (speedup 1.0000x reference)
#include <cuda_runtime.h>
#include <cuda_bf16.h>

// out = -0.1f * x over 67,108,864 fp32 elements (256 MiB in + 256 MiB out).
// Pure HBM stream. Best measured structure: ITEMS=2 x THREADS=512 float4
// (73.8 us kernel, 81-82% DRAM). This round: write-through stores
// (st.global.wt) — output is write-once, so skip L2 dirty-line writeback
// scheduling and present the memory controller with immediate full-line
// writes (fewer read/write bus turnarounds).
// Sweep history (kernel us): 1x256=79.2, 4x256=74.7, 4x512=74.0, 2x512=73.8,
// 2x256=75.1, 8x256=75.2, v8 2x512=74.6, persistent=80.1.

#define ITEMS 2
#define THREADS 512
#define TILE (THREADS * ITEMS)

// Exact-fit: grid covers n4 exactly, no bounds checks.
__global__ void __launch_bounds__(THREADS)
scale_kernel_exact(const float4* __restrict__ x,
                   float4* __restrict__ out) {
    int base = blockIdx.x * TILE + threadIdx.x;

    float4 v[ITEMS];
    #pragma unroll
    for (int k = 0; k < ITEMS; k++) {
        v[k] = __ldcs(&x[base + k * THREADS]);
    }

    #pragma unroll
    for (int k = 0; k < ITEMS; k++) {
        float4 r;
        r.x = -0.1f * v[k].x;
        r.y = -0.1f * v[k].y;
        r.z = -0.1f * v[k].z;
        r.w = -0.1f * v[k].w;
        __stwt(&out[base + k * THREADS], r);
    }
}

// Guarded generic kernel for sizes that don't divide into whole tiles.
__global__ void __launch_bounds__(THREADS)
scale_kernel_guarded(const float4* __restrict__ x,
                     float4* __restrict__ out,
                     int n4) {
    int base = blockIdx.x * TILE + threadIdx.x;
    #pragma unroll
    for (int k = 0; k < ITEMS; k++) {
        int i = base + k * THREADS;
        if (i < n4) {
            float4 v = __ldcs(&x[i]);
            float4 r;
            r.x = -0.1f * v.x;
            r.y = -0.1f * v.y;
            r.z = -0.1f * v.z;
            r.w = -0.1f * v.w;
            __stwt(&out[i], r);
        }
    }
}

// Scalar tail for element counts not divisible by 4.
__global__ void scale_kernel_tail(const float* __restrict__ x,
                                  float* __restrict__ out,
                                  int start, int n) {
    int i = start + blockIdx.x * blockDim.x + threadIdx.x;
    if (i < n) {
        out[i] = -0.1f * x[i];
    }
}

extern "C" void kernel_launch(void* const* d_in, const int* in_sizes, int n_in,
                              void* d_out, int out_size) {
    const float* x = (const float*)d_in[0];
    float* out = (float*)d_out;
    int n = in_sizes[0];

    int n4 = n / 4;
    if (n4 > 0) {
        if (n4 % TILE == 0) {
            scale_kernel_exact<<<n4 / TILE, THREADS>>>(
                (const float4*)x, (float4*)out);
        } else {
            int blocks = (n4 + TILE - 1) / TILE;
            scale_kernel_guarded<<<blocks, THREADS>>>(
                (const float4*)x, (float4*)out, n4);
        }
    }
    int tail_start = n4 * 4;
    int tail = n - tail_start;
    if (tail > 0) {
        scale_kernel_tail<<<1, 256>>>(x, out, tail_start, n);
    }
}

// round 10
// speedup vs baseline: 1.0066x; 1.0066x over previous
#include <cuda_runtime.h>
#include <cuda_bf16.h>

// out = -0.1f * x over 67,108,864 fp32 elements (256 MiB in + 256 MiB out).
// Pure HBM stream at the bidirectional read+write turnaround ceiling:
// ~6.5 TB/s = 82% of 8 TB/s spec. FINAL kernel — measured optimum of the
// full config sweep:
//   (kernel us) 2x512=73.8*, 4x512=74.0, v8=74.6, 4x256=74.7, 2x256=75.1,
//   8x256=75.2, wt-stores=75.4, 1x256=79.2, persistent=80.1
// Structure: float4 (LDG.128/STG.128), 2 front-batched streaming loads per
// thread, streaming stores, exact-fit grid with no predication.

#define ITEMS 2
#define THREADS 512
#define TILE (THREADS * ITEMS)

// Exact-fit: grid covers n4 exactly, no bounds checks.
__global__ void __launch_bounds__(THREADS)
scale_kernel_exact(const float4* __restrict__ x,
                   float4* __restrict__ out) {
    int base = blockIdx.x * TILE + threadIdx.x;

    float4 v[ITEMS];
    #pragma unroll
    for (int k = 0; k < ITEMS; k++) {
        v[k] = __ldcs(&x[base + k * THREADS]);
    }

    #pragma unroll
    for (int k = 0; k < ITEMS; k++) {
        float4 r;
        r.x = -0.1f * v[k].x;
        r.y = -0.1f * v[k].y;
        r.z = -0.1f * v[k].z;
        r.w = -0.1f * v[k].w;
        __stcs(&out[base + k * THREADS], r);
    }
}

// Guarded generic kernel for sizes that don't divide into whole tiles.
__global__ void __launch_bounds__(THREADS)
scale_kernel_guarded(const float4* __restrict__ x,
                     float4* __restrict__ out,
                     int n4) {
    int base = blockIdx.x * TILE + threadIdx.x;
    #pragma unroll
    for (int k = 0; k < ITEMS; k++) {
        int i = base + k * THREADS;
        if (i < n4) {
            float4 v = __ldcs(&x[i]);
            float4 r;
            r.x = -0.1f * v.x;
            r.y = -0.1f * v.y;
            r.z = -0.1f * v.z;
            r.w = -0.1f * v.w;
            __stcs(&out[i], r);
        }
    }
}

// Scalar tail for element counts not divisible by 4.
__global__ void scale_kernel_tail(const float* __restrict__ x,
                                  float* __restrict__ out,
                                  int start, int n) {
    int i = start + blockIdx.x * blockDim.x + threadIdx.x;
    if (i < n) {
        out[i] = -0.1f * x[i];
    }
}

extern "C" void kernel_launch(void* const* d_in, const int* in_sizes, int n_in,
                              void* d_out, int out_size) {
    const float* x = (const float*)d_in[0];
    float* out = (float*)d_out;
    int n = in_sizes[0];

    int n4 = n / 4;
    if (n4 > 0) {
        if (n4 % TILE == 0) {
            scale_kernel_exact<<<n4 / TILE, THREADS>>>(
                (const float4*)x, (float4*)out);
        } else {
            int blocks = (n4 + TILE - 1) / TILE;
            scale_kernel_guarded<<<blocks, THREADS>>>(
                (const float4*)x, (float4*)out, n4);
        }
    }
    int tail_start = n4 * 4;
    int tail = n - tail_start;
    if (tail > 0) {
        scale_kernel_tail<<<1, 256>>>(x, out, tail_start, n);
    }
}

// round 11
// speedup vs baseline: 1.0182x; 1.0115x over previous
#include <cuda_runtime.h>
#include <cuda_bf16.h>

// out = -0.1f * x over 67,108,864 fp32 elements (256 MiB in + 256 MiB out).
// FINAL kernel — at the HBM roofline: ~6.45 TB/s sustained = 81-82% of the
// 8 TB/s spec, which is the bidirectional read+write turnaround ceiling for
// a 1:1 stream. Run-to-run noise is +/-1 us; the full sweep (vector width
// 128/256-bit, unroll 1-8, blocks 256/512, occupancy 57-80%, flat vs
// persistent grid, .cs/.wt policies) is flat within that noise:
//   (kernel us) 2x512=73.8-74.9*, 4x512=74.0, v8=74.6, 4x256=74.7,
//   2x256=75.1, 8x256=75.2, wt-stores=75.4, 1x256=79.2, persistent=80.1
// Structure: LDG.E.128.CS x2 front-batched per thread, FMUL, STG.E.128.CS,
// exact-fit grid with no predication.

#define ITEMS 2
#define THREADS 512
#define TILE (THREADS * ITEMS)

// Exact-fit: grid covers n4 exactly, no bounds checks.
__global__ void __launch_bounds__(THREADS)
scale_kernel_exact(const float4* __restrict__ x,
                   float4* __restrict__ out) {
    int base = blockIdx.x * TILE + threadIdx.x;

    float4 v[ITEMS];
    #pragma unroll
    for (int k = 0; k < ITEMS; k++) {
        v[k] = __ldcs(&x[base + k * THREADS]);
    }

    #pragma unroll
    for (int k = 0; k < ITEMS; k++) {
        float4 r;
        r.x = -0.1f * v[k].x;
        r.y = -0.1f * v[k].y;
        r.z = -0.1f * v[k].z;
        r.w = -0.1f * v[k].w;
        __stcs(&out[base + k * THREADS], r);
    }
}

// Guarded generic kernel for sizes that don't divide into whole tiles.
__global__ void __launch_bounds__(THREADS)
scale_kernel_guarded(const float4* __restrict__ x,
                     float4* __restrict__ out,
                     int n4) {
    int base = blockIdx.x * TILE + threadIdx.x;
    #pragma unroll
    for (int k = 0; k < ITEMS; k++) {
        int i = base + k * THREADS;
        if (i < n4) {
            float4 v = __ldcs(&x[i]);
            float4 r;
            r.x = -0.1f * v.x;
            r.y = -0.1f * v.y;
            r.z = -0.1f * v.z;
            r.w = -0.1f * v.w;
            __stcs(&out[i], r);
        }
    }
}

// Scalar tail for element counts not divisible by 4.
__global__ void scale_kernel_tail(const float* __restrict__ x,
                                  float* __restrict__ out,
                                  int start, int n) {
    int i = start + blockIdx.x * blockDim.x + threadIdx.x;
    if (i < n) {
        out[i] = -0.1f * x[i];
    }
}

extern "C" void kernel_launch(void* const* d_in, const int* in_sizes, int n_in,
                              void* d_out, int out_size) {
    const float* x = (const float*)d_in[0];
    float* out = (float*)d_out;
    int n = in_sizes[0];

    int n4 = n / 4;
    if (n4 > 0) {
        if (n4 % TILE == 0) {
            scale_kernel_exact<<<n4 / TILE, THREADS>>>(
                (const float4*)x, (float4*)out);
        } else {
            int blocks = (n4 + TILE - 1) / TILE;
            scale_kernel_guarded<<<blocks, THREADS>>>(
                (const float4*)x, (float4*)out, n4);
        }
    }
    int tail_start = n4 * 4;
    int tail = n - tail_start;
    if (tail > 0) {
        scale_kernel_tail<<<1, 256>>>(x, out, tail_start, n);
    }
}